// round 5
// baseline (speedup 1.0000x reference)
#include <cuda_runtime.h>
#include <cuda_bf16.h>
#include <cstdint>

// ---------------------------------------------------------------------------
// GraphSAGE: 3x (SAGEConv mean-aggr -> LayerNorm -> ReLU), mean|max pool, MLP.
//
// Per layer (linearity of mean aggregation):
//   y = x @ [Wl^T | Wr^T]            dense GEMM, K=128, F2=2*Fout (FFMA2 path)
//   h = relu(LN( mean_{j in N(i)} yl[j] + bl + yr[i] ) * g + be)
// CSR (by dst) built per launch. edge_index / batch are INT32 (JAX x64 off).
// No runtime API calls in kernel_launch except kernel launches; all scratch
// is __device__ globals referenced directly in device code; static smem only.
// ---------------------------------------------------------------------------

#define NGRAPH 64

// ------------------------- device scratch (static) -------------------------
__device__ __align__(16) float g_y   [50048 * 256];   // GEMM out (yl|yr), widest
__device__ __align__(16) float g_h1  [50048 * 128];   // layer outputs (ping)
__device__ __align__(16) float g_h2  [50048 * 128];   // layer outputs (pong)
__device__ int   g_deg [50048];
__device__ int   g_rowptr[50052];
__device__ int   g_cursor[50048];
__device__ int   g_col [600064];
__device__ __align__(16) float g_wt0 [128 * 256];     // W pre-transposed [k][o]
__device__ __align__(16) float g_wt1 [128 * 256];
__device__ __align__(16) float g_wt2 [128 * 128];
__device__ __align__(16) float g_pool[NGRAPH * 128];  // [mean(64)|max(64)]/graph

// ------------------------------ small helpers ------------------------------
union F2U { unsigned long long u; float2 f; };

__device__ __forceinline__ unsigned long long ffma2(unsigned long long a,
                                                    unsigned long long b,
                                                    unsigned long long c) {
    unsigned long long d;
    asm("fma.rn.f32x2 %0, %1, %2, %3;" : "=l"(d) : "l"(a), "l"(b), "l"(c));
    return d;
}

// ------------------------------ preprocessing ------------------------------
__global__ void zero_deg_kernel(int n) {
    int i = blockIdx.x * blockDim.x + threadIdx.x;
    if (i < n) g_deg[i] = 0;
}

__global__ void count_deg_kernel(const int* __restrict__ ei, int E) {
    int e = blockIdx.x * blockDim.x + threadIdx.x;
    if (e < E) atomicAdd(&g_deg[ei[E + e]], 1);
}

// single 1024-thread block: rowptr (shifted inclusive) + cursor (exclusive)
__global__ void scan_kernel(int N) {
    __shared__ int s[1024];
    int tid = threadIdx.x;
    if (tid == 0) g_rowptr[0] = 0;
    int carry = 0;
    for (int base = 0; base < N; base += 8192) {
        int loc[8];
        int lsum = 0;
#pragma unroll
        for (int j = 0; j < 8; j++) {
            int i = base + tid * 8 + j;
            loc[j] = (i < N) ? g_deg[i] : 0;
            lsum += loc[j];
        }
        s[tid] = lsum;
        __syncthreads();
        for (int off = 1; off < 1024; off <<= 1) {
            int v = (tid >= off) ? s[tid - off] : 0;
            __syncthreads();
            s[tid] += v;
            __syncthreads();
        }
        int run = carry + s[tid] - lsum;   // exclusive prefix for this thread
#pragma unroll
        for (int j = 0; j < 8; j++) {
            int i = base + tid * 8 + j;
            if (i < N) {
                g_cursor[i] = run;
                run += loc[j];
                g_rowptr[i + 1] = run;
            }
        }
        int tot = s[1023];
        __syncthreads();
        carry += tot;
    }
}

__global__ void scatter_kernel(const int* __restrict__ ei, int E) {
    int e = blockIdx.x * blockDim.x + threadIdx.x;
    if (e < E) {
        int sN = ei[e];
        int d  = ei[E + e];
        int p  = atomicAdd(&g_cursor[d], 1);
        g_col[p] = sN;
    }
}

// Wt[k][o] = (o < F) ? Wl[o][k] : Wr[o-F][k]; K = 128
template <int SEL>
__global__ void wtrans_kernel(const float* __restrict__ Wl,
                              const float* __restrict__ Wr, int F) {
    float* Wt = (SEL == 0) ? g_wt0 : (SEL == 1) ? g_wt1 : g_wt2;
    int F2 = 2 * F;
    int total = 128 * F2;
    for (int idx = blockIdx.x * blockDim.x + threadIdx.x; idx < total;
         idx += gridDim.x * blockDim.x) {
        int k = idx / F2;
        int o = idx % F2;
        Wt[idx] = (o < F) ? Wl[o * 128 + k] : Wr[(o - F) * 128 + k];
    }
}

// ------------------------------- dense GEMM --------------------------------
// Y[N,F2] = X[N,128] @ W[128,F2] via packed fp32 (fma.rn.f32x2 -> FFMA2).
// 256 threads, BM=32. X tile stored transposed AND value-duplicated in smem
// (float2 {v,v}) so FFMA2 'a' operands need no pack MOVs. W streamed from
// global (L1-resident; every block rereads the same 64/128 KB).
// Micro-tile: 4 rows x BNT cols per thread (warp-uniform rows -> LDS bcast).
template <int F2, int XSEL, int WSEL>
__global__ void __launch_bounds__(256) gemm_kernel(const float* __restrict__ Xin,
                                                   int N) {
    constexpr int BNT = F2 / 32;             // 8 (F2=256) or 4 (F2=128)
    constexpr int NP  = BNT / 2;             // packed col-pairs per thread
    __shared__ __align__(16) float2 xs[128 * 32];   // [k][m] dup pairs, 32 KB

    const float* X = (XSEL == 0) ? Xin : (XSEL == 1) ? g_h1 : g_h2;
    const float* W = (WSEL == 0) ? g_wt0 : (WSEL == 1) ? g_wt1 : g_wt2;

    const int tid = threadIdx.x;
    const int bm  = blockIdx.x * 32;

    // load X tile: dup-store transposed
#pragma unroll
    for (int i = 0; i < 4; i++) {
        int idx = tid + 256 * i;       // 0..1023
        int m   = idx & 31;            // row in tile
        int k4  = idx >> 5;            // k-group (0..31)
        float4 v = make_float4(0.f, 0.f, 0.f, 0.f);
        int row = bm + m;
        if (row < N)
            v = *reinterpret_cast<const float4*>(X + (size_t)row * 128 + k4 * 4);
        xs[(4 * k4 + 0) * 32 + m] = make_float2(v.x, v.x);
        xs[(4 * k4 + 1) * 32 + m] = make_float2(v.y, v.y);
        xs[(4 * k4 + 2) * 32 + m] = make_float2(v.z, v.z);
        xs[(4 * k4 + 3) * 32 + m] = make_float2(v.w, v.w);
    }
    __syncthreads();

    const int m0 = (tid >> 5) * 4;       // warp-uniform row block (0..28)
    const int o0 = (tid & 31) * BNT;     // per-lane column block

    unsigned long long c2[4][NP];
#pragma unroll
    for (int i = 0; i < 4; i++)
#pragma unroll
        for (int p = 0; p < NP; p++) c2[i][p] = 0ull;

#pragma unroll 8
    for (int k = 0; k < 128; k++) {
        // a: 4 duplicated row-pairs (LDS.128 broadcast x2)
        ulonglong2 aa0 = *reinterpret_cast<const ulonglong2*>(&xs[k * 32 + m0]);
        ulonglong2 aa1 = *reinterpret_cast<const ulonglong2*>(&xs[k * 32 + m0 + 2]);
        unsigned long long a[4] = {aa0.x, aa0.y, aa1.x, aa1.y};
        // b: BNT contiguous outputs as NP packed pairs (LDG.128, L1 hit)
        unsigned long long b[NP];
        {
            ulonglong2 bb0 = *reinterpret_cast<const ulonglong2*>(W + (size_t)k * F2 + o0);
            b[0] = bb0.x; b[1] = bb0.y;
            if (NP == 4) {
                ulonglong2 bb1 = *reinterpret_cast<const ulonglong2*>(W + (size_t)k * F2 + o0 + 4);
                b[2] = bb1.x; b[3] = bb1.y;
            }
        }
#pragma unroll
        for (int i = 0; i < 4; i++)
#pragma unroll
            for (int p = 0; p < NP; p++) c2[i][p] = ffma2(a[i], b[p], c2[i][p]);
    }

#pragma unroll
    for (int i = 0; i < 4; i++) {
        int row = bm + m0 + i;
        if (row < N) {
#pragma unroll
            for (int p = 0; p < NP; p += 2) {
                F2U u0, u1;
                u0.u = c2[i][p];
                u1.u = c2[i][p + 1];
                float4 v = make_float4(u0.f.x, u0.f.y, u1.f.x, u1.f.y);
                *reinterpret_cast<float4*>(g_y + (size_t)row * F2 + o0 + 2 * p) = v;
            }
        }
    }
}

// ------------------- fused aggregation + LayerNorm + ReLU -------------------
// One warp per node; gathers neighbor yl rows from L2-resident g_y.
template <int F, int OSEL>   // F: 128 or 64; OSEL: 1 -> g_h1, 2 -> g_h2
__global__ void agg_ln_kernel(const float* __restrict__ bl,
                              const float* __restrict__ gm,
                              const float* __restrict__ be, int N) {
    constexpr int F2  = 2 * F;
    constexpr int VPL = F / 32;   // floats per lane
    float* Hout = (OSEL == 1) ? g_h1 : g_h2;
    int warp = (blockIdx.x * blockDim.x + threadIdx.x) >> 5;
    int lane = threadIdx.x & 31;
    if (warp >= N) return;

    int r0 = g_rowptr[warp], r1 = g_rowptr[warp + 1];
    float acc[VPL];
#pragma unroll
    for (int i = 0; i < VPL; i++) acc[i] = 0.f;

    for (int e0 = r0; e0 < r1; e0 += 32) {
        int j = 0;
        if (e0 + lane < r1) j = g_col[e0 + lane];
        int cnt = min(32, r1 - e0);
        for (int t = 0; t < cnt; t++) {
            int jj = __shfl_sync(0xffffffffu, j, t);
            const float* p = g_y + (size_t)jj * F2 + lane * VPL;
            if (VPL == 4) {
                float4 v = *reinterpret_cast<const float4*>(p);
                acc[0] += v.x; acc[1] += v.y; acc[2] += v.z; acc[3] += v.w;
            } else {
                float2 v = *reinterpret_cast<const float2*>(p);
                acc[0] += v.x; acc[1] += v.y;
            }
        }
    }

    float invd = 1.0f / (float)max(r1 - r0, 1);
    const float* yr = g_y + (size_t)warp * F2 + F + lane * VPL;
    float v[VPL];
#pragma unroll
    for (int i = 0; i < VPL; i++) v[i] = acc[i] * invd + yr[i] + bl[lane * VPL + i];

    float s = 0.f;
#pragma unroll
    for (int i = 0; i < VPL; i++) s += v[i];
#pragma unroll
    for (int off = 16; off > 0; off >>= 1) s += __shfl_xor_sync(0xffffffffu, s, off);
    float mu = s * (1.0f / F);

    float q = 0.f;
#pragma unroll
    for (int i = 0; i < VPL; i++) { float d = v[i] - mu; q += d * d; }
#pragma unroll
    for (int off = 16; off > 0; off >>= 1) q += __shfl_xor_sync(0xffffffffu, q, off);
    float rstd = rsqrtf(q * (1.0f / F) + 1e-5f);

    float* out = Hout + (size_t)warp * F + lane * VPL;
#pragma unroll
    for (int i = 0; i < VPL; i++) {
        float o = (v[i] - mu) * rstd * gm[lane * VPL + i] + be[lane * VPL + i];
        out[i] = fmaxf(o, 0.f);
    }
}

// ------------------------ graph pooling (mean | max) ------------------------
__device__ __forceinline__ int lbound32(const int* b, int n, int v) {
    int lo = 0, hi = n;
    while (lo < hi) {
        int mid = (lo + hi) >> 1;
        if (b[mid] < v) lo = mid + 1; else hi = mid;
    }
    return lo;
}

__global__ void pool_kernel(const int* __restrict__ batch, int N) {
    int g = blockIdx.x;                      // one block per graph (batch sorted)
    int s = lbound32(batch, N, g);
    int e = lbound32(batch, N, g + 1);
    int f = threadIdx.x & 63;
    int r = threadIdx.x >> 6;                // 4 node-lanes per feature
    float sum = 0.f, mx = 0.f;               // post-relu => max >= 0
    for (int i = s + r; i < e; i += 4) {
        float v = g_h1[(size_t)i * 64 + f];
        sum += v;
        mx = fmaxf(mx, v);
    }
    __shared__ float ssum[4][64], smax[4][64];
    ssum[r][f] = sum;
    smax[r][f] = mx;
    __syncthreads();
    if (r == 0) {
        float S = ssum[0][f] + ssum[1][f] + ssum[2][f] + ssum[3][f];
        float M = fmaxf(fmaxf(smax[0][f], smax[1][f]), fmaxf(smax[2][f], smax[3][f]));
        float invc = 1.0f / (float)max(e - s, 1);
        g_pool[g * 128 + f]      = S * invc;  // mean
        g_pool[g * 128 + 64 + f] = M;         // max
    }
}

// --------------------------------- MLP head ---------------------------------
__global__ void head_kernel(const float* __restrict__ cW1, const float* __restrict__ cb1,
                            const float* __restrict__ cW2, const float* __restrict__ cb2,
                            float* __restrict__ out) {
    int g = blockIdx.x;
    int t = threadIdx.x;   // 128 threads
    __shared__ float zs[128], s1[128];
    zs[t] = g_pool[g * 128 + t];
    __syncthreads();
    float acc = cb1[t];
    const float* w = cW1 + t * 128;
#pragma unroll 8
    for (int k = 0; k < 128; k++) acc += zs[k] * w[k];
    s1[t] = fmaxf(acc, 0.f);
    __syncthreads();
    if (t < 2) {
        float a = cb2[t];
        const float* w2 = cW2 + t * 128;
        for (int k = 0; k < 128; k++) a += s1[k] * w2[k];
        out[g * 2 + t] = a;
    }
}

// --------------------------------- launcher ---------------------------------
// ONLY kernel launches here: no symbol queries, no attribute sets, no memcpy.
extern "C" void kernel_launch(void* const* d_in, const int* in_sizes, int n_in,
                              void* d_out, int out_size) {
    const float* x     = (const float*)d_in[0];
    const int*   ei    = (const int*)d_in[1];    // int32! (JAX x64 disabled)
    const int*   batch = (const int*)d_in[2];    // int32!
    const float *Wl0 = (const float*)d_in[3],  *bl0 = (const float*)d_in[4],
                *Wr0 = (const float*)d_in[5],  *g0  = (const float*)d_in[6],
                *be0 = (const float*)d_in[7];
    const float *Wl1 = (const float*)d_in[8],  *bl1 = (const float*)d_in[9],
                *Wr1 = (const float*)d_in[10], *g1  = (const float*)d_in[11],
                *be1 = (const float*)d_in[12];
    const float *Wl2 = (const float*)d_in[13], *bl2 = (const float*)d_in[14],
                *Wr2 = (const float*)d_in[15], *g2  = (const float*)d_in[16],
                *be2 = (const float*)d_in[17];
    const float *cW1 = (const float*)d_in[18], *cb1 = (const float*)d_in[19],
                *cW2 = (const float*)d_in[20], *cb2 = (const float*)d_in[21];
    float* out = (float*)d_out;

    const int N = in_sizes[0] / 128;
    const int E = in_sizes[1] / 2;

    // --- CSR build ---
    zero_deg_kernel<<<(N + 255) / 256, 256>>>(N);
    count_deg_kernel<<<(E + 255) / 256, 256>>>(ei, E);
    scan_kernel<<<1, 1024>>>(N);
    scatter_kernel<<<(E + 255) / 256, 256>>>(ei, E);

    // --- weight pre-transpose: [k][o] concat of [Wl^T | Wr^T] ---
    wtrans_kernel<0><<<128, 256>>>(Wl0, Wr0, 128);
    wtrans_kernel<1><<<128, 256>>>(Wl1, Wr1, 128);
    wtrans_kernel<2><<<64, 256>>>(Wl2, Wr2, 64);

    const int gemmGrid = (N + 31) / 32;
    const int aggGrid  = (N + 7) / 8;   // 8 warps / 256-thread block

    // --- layer 0: x[N,128] -> g_h1[N,128] ---
    gemm_kernel<256, 0, 0><<<gemmGrid, 256>>>(x, N);
    agg_ln_kernel<128, 1><<<aggGrid, 256>>>(bl0, g0, be0, N);

    // --- layer 1: g_h1 -> g_h2 ---
    gemm_kernel<256, 1, 1><<<gemmGrid, 256>>>(nullptr, N);
    agg_ln_kernel<128, 2><<<aggGrid, 256>>>(bl1, g1, be1, N);

    // --- layer 2: g_h2 -> g_h1 (reused as [N,64]) ---
    gemm_kernel<128, 2, 2><<<gemmGrid, 256>>>(nullptr, N);
    agg_ln_kernel<64, 1><<<aggGrid, 256>>>(bl2, g2, be2, N);

    // --- readout + head ---
    pool_kernel<<<NGRAPH, 256>>>(batch, N);
    head_kernel<<<NGRAPH, 128>>>(cW1, cb1, cW2, cb2, out);
}